// round 1
// baseline (speedup 1.0000x reference)
#include <cuda_runtime.h>
#include <cuda_bf16.h>
#include <math.h>

// Problem constants
#define BS 4096
#define HL 20
#define NF 128
#define EF 128
#define TF 128
#define DM 640          // 3*NF + EF + TF
#define DIN 512         // DM - TF
#define NHEAD 2
#define DH 320          // DM / NHEAD
#define ODE_STEPS 8

// ---------------- scratch (device globals; no allocation allowed) ----------
__device__ float g_full [(size_t)BS*HL*DM];     // full_vals  [BS,HL,640]
__device__ float g_nb   [(size_t)BS*HL*384];    // nb         [BS,HL,384]
__device__ float g_kv   [(size_t)BS*HL*1280];   // k|v        [BS,HL,1280]
__device__ float g_lef  [(size_t)BS*DIN];       // last_event_feat
__device__ float g_qlast[(size_t)BS*DM];
__device__ float g_ctx  [(size_t)BS*DM];
__device__ float g_mha  [(size_t)BS*DM];
__device__ float g_qn   [(size_t)BS*NF];
__device__ float g_qh   [(size_t)BS*NF];
__device__ float g_kh   [(size_t)BS*HL*NF];
__device__ float g_vh   [(size_t)BS*HL*NF];
__device__ float g_gi   [(size_t)BS*384];
__device__ float g_hpr  [(size_t)BS*NF];
__device__ float g_odewT[NF*NF];

// ---------------- build full_vals, nb, last_event_feat ---------------------
__global__ void build_kernel(const int* __restrict__ nids,
                             const int* __restrict__ hist_nids,
                             const int* __restrict__ aids,
                             const int* __restrict__ eids,
                             const float* __restrict__ hist_ts,
                             const int* __restrict__ dirs,
                             const float* __restrict__ node_feat,
                             const float* __restrict__ edge_feat,
                             const float* __restrict__ anony,
                             const float* __restrict__ tw,
                             const float* __restrict__ tb)
{
    int bl = blockIdx.x;            // b*HL + l
    int b  = bl / HL, l = bl % HL;
    int j  = threadIdx.x;           // 0..127
    int hn  = hist_nids[bl];
    int dir = dirs[bl];
    int nid = nids[b];
    int src = dir ? nid : hn;
    int dst = dir ? hn  : nid;
    float sv = node_feat[(size_t)src*NF + j];
    float dv = node_feat[(size_t)dst*NF + j];
    float av = anony[(size_t)aids[bl]*NF + j];
    float ev = edge_feat[(size_t)eids[bl]*EF + j];
    float dt = hist_ts[b*HL + HL-1] - hist_ts[bl];
    float tv = cosf(dt*tw[j] + tb[j]);

    float* fv = g_full + (size_t)bl*DM;
    if (l == HL-1) {
        float* lef = g_lef + (size_t)b*DIN;
        lef[j] = sv; lef[NF+j] = dv; lef[2*NF+j] = av; lef[3*NF+j] = ev;
        fv[j] = 0.f; fv[NF+j] = 0.f; fv[2*NF+j] = 0.f; fv[3*NF+j] = 0.f;
        fv[4*NF+j] = tv;
    } else {
        fv[j] = sv; fv[NF+j] = dv; fv[2*NF+j] = av; fv[3*NF+j] = ev;
        fv[4*NF+j] = tv;
    }
    float* nb = g_nb + (size_t)bl*384;
    nb[j]        = node_feat[(size_t)hn*NF + j];
    nb[NF + j]   = ev;
    nb[2*NF + j] = tv;
}

__global__ void transpose_odew(const float* __restrict__ w)
{
    int idx = blockIdx.x*128 + threadIdx.x;   // 16384 total
    int j = idx >> 7, k = idx & 127;
    g_odewT[k*NF + j] = w[idx];
}

// ---------------- generic register-tiled SGEMM ------------------------------
// TRANSB=1: C[M,N] = A[M,K] * B[N,K]^T + bias   (B row-major (N,K))
// TRANSB=0: C[M,N] = A[M,K] * B[K,N]   + bias   (B row-major (K,N))
// requires M%128==0, N%128==0, K%8==0
template<bool TRANSB>
__global__ __launch_bounds__(256)
void sgemm_kernel(int M, int N, int K,
                  const float* __restrict__ A, int lda,
                  const float* __restrict__ B,
                  float* __restrict__ C, int ldc,
                  const float* __restrict__ bias)
{
    __shared__ float As[8][128];
    __shared__ float Bs[8][128];
    int tid = threadIdx.x;
    int row0 = blockIdx.y * 128;
    int col0 = blockIdx.x * 128;
    int tx = tid & 15, ty = tid >> 4;

    float acc[8][8];
#pragma unroll
    for (int i = 0; i < 8; i++)
#pragma unroll
        for (int j = 0; j < 8; j++) acc[i][j] = 0.f;

    for (int k0 = 0; k0 < K; k0 += 8) {
        {   // load A tile 128x8, transpose into As[k][m]
            int r = tid >> 1, c4 = (tid & 1) * 4;
            float4 v = *(const float4*)(A + (size_t)(row0 + r)*lda + k0 + c4);
            As[c4+0][r] = v.x; As[c4+1][r] = v.y; As[c4+2][r] = v.z; As[c4+3][r] = v.w;
        }
        if (TRANSB) {
            int r = tid >> 1, c4 = (tid & 1) * 4;
            float4 v = *(const float4*)(B + (size_t)(col0 + r)*K + k0 + c4);
            Bs[c4+0][r] = v.x; Bs[c4+1][r] = v.y; Bs[c4+2][r] = v.z; Bs[c4+3][r] = v.w;
        } else {
            int r = tid >> 5, c4 = (tid & 31) * 4;
            *(float4*)&Bs[r][c4] = *(const float4*)(B + (size_t)(k0 + r)*N + col0 + c4);
        }
        __syncthreads();
#pragma unroll
        for (int kk = 0; kk < 8; kk++) {
            float4 a0 = *(const float4*)&As[kk][ty*8];
            float4 a1 = *(const float4*)&As[kk][ty*8+4];
            float4 b0 = *(const float4*)&Bs[kk][tx*8];
            float4 b1 = *(const float4*)&Bs[kk][tx*8+4];
            float a[8] = {a0.x,a0.y,a0.z,a0.w,a1.x,a1.y,a1.z,a1.w};
            float bb[8] = {b0.x,b0.y,b0.z,b0.w,b1.x,b1.y,b1.z,b1.w};
#pragma unroll
            for (int i = 0; i < 8; i++)
#pragma unroll
                for (int j = 0; j < 8; j++) acc[i][j] = fmaf(a[i], bb[j], acc[i][j]);
        }
        __syncthreads();
    }

#pragma unroll
    for (int i = 0; i < 8; i++) {
        size_t r = (size_t)(row0 + ty*8 + i);
#pragma unroll
        for (int j = 0; j < 8; j++) {
            int c = col0 + tx*8 + j;
            float v = acc[i][j];
            if (bias) v += bias[c];
            C[r*ldc + c] = v;
        }
    }
}

// ---------------- attention 1 (query = last position) ----------------------
__global__ void attn1_kernel(const int* __restrict__ hist_nids)
{
    int b = blockIdx.x, tid = threadIdx.x;   // 256 threads
    __shared__ float sq[DM];
    __shared__ float sS[NHEAD*HL];
    __shared__ float sA[NHEAD*HL];
    for (int d = tid; d < DM; d += 256) sq[d] = g_qlast[(size_t)b*DM + d];
    __syncthreads();

    int warp = tid >> 5, lane = tid & 31;
    for (int p = warp; p < NHEAD*HL; p += 8) {
        int h = p / HL, m = p % HL;
        const float* krow = g_kv + (size_t)(b*HL + m)*1280 + h*DH;
        const float* qrow = sq + h*DH;
        float s = 0.f;
#pragma unroll
        for (int i = 0; i < 10; i++) { int d = lane + i*32; s += qrow[d]*krow[d]; }
#pragma unroll
        for (int o = 16; o; o >>= 1) s += __shfl_xor_sync(0xffffffffu, s, o);
        if (!lane) sS[p] = s * 0.05590169943749474f;   // 1/sqrt(320)
    }
    __syncthreads();
    if (tid < NHEAD) {
        int h = tid;
        float sc[HL], mx = -1e30f;
        for (int m = 0; m < HL; m++) {
            float v = sS[h*HL + m];
            if (hist_nids[b*HL + m] == 0 && m != HL-1) v = -1e9f;
            sc[m] = v; mx = fmaxf(mx, v);
        }
        float sum = 0.f;
        for (int m = 0; m < HL; m++) { float e = expf(sc[m]-mx); sc[m] = e; sum += e; }
        float inv = 1.f/sum;
        for (int m = 0; m < HL; m++) sA[h*HL + m] = sc[m]*inv;
    }
    __syncthreads();
    for (int d = tid; d < DM; d += 256) {
        int h = d / DH;
        const float* vbase = g_kv + (size_t)b*HL*1280 + 640 + d;
        float accv = 0.f;
#pragma unroll
        for (int m = 0; m < HL; m++) accv += sA[h*HL + m] * vbase[(size_t)m*1280];
        g_ctx[(size_t)b*DM + d] = accv;
    }
}

// ---------------- attention 2 + merge + GRU ---------------------------------
__global__ void attn2_gru_kernel(const int* __restrict__ nids,
                                 const int* __restrict__ hist_nids,
                                 const float* __restrict__ hist_ts,
                                 const float* __restrict__ node_feat,
                                 const float* __restrict__ merge_w,
                                 const float* __restrict__ merge_b,
                                 const float* __restrict__ gwhh,
                                 const float* __restrict__ gbhh,
                                 float* __restrict__ out)
{
    int b = blockIdx.x, tid = threadIdx.x;   // 128 threads
    __shared__ float sqh[NF], ssc[HL], sa[HL], scat[2*NF], shpl[NF];
    sqh[tid] = g_qh[(size_t)b*NF + tid];
    __syncthreads();
    int warp = tid >> 5, lane = tid & 31;
    for (int l = warp; l < HL; l += 4) {
        const float* kr = g_kh + (size_t)(b*HL + l)*NF;
        float s = 0.f;
#pragma unroll
        for (int i = 0; i < 4; i++) { int d = lane + i*32; s += sqh[d]*kr[d]; }
#pragma unroll
        for (int o = 16; o; o >>= 1) s += __shfl_xor_sync(0xffffffffu, s, o);
        if (!lane) ssc[l] = s * 0.08838834764831845f;  // 1/sqrt(128)
    }
    __syncthreads();
    if (tid == 0) {
        float sc[HL], mx = -1e30f;
        for (int l = 0; l < HL; l++) {
            float v = ssc[l];
            if (hist_nids[b*HL + l] == 0 && l != HL-1) v = -1e9f;
            sc[l] = v; mx = fmaxf(mx, v);
        }
        float sum = 0.f;
        for (int l = 0; l < HL; l++) { float e = expf(sc[l]-mx); sc[l] = e; sum += e; }
        float inv = 1.f/sum;
        for (int l = 0; l < HL; l++) sa[l] = sc[l]*inv;
    }
    __syncthreads();
    float c2 = 0.f;
#pragma unroll
    for (int l = 0; l < HL; l++) c2 += sa[l] * g_vh[(size_t)(b*HL + l)*NF + tid];
    scat[tid]      = c2;
    scat[NF + tid] = node_feat[(size_t)nids[b]*NF + tid];
    __syncthreads();

    float acc = merge_b[tid];
#pragma unroll 8
    for (int k = 0; k < 2*NF; k++) acc = fmaf(scat[k], merge_w[k*NF + tid], acc);
    float hpl = tanhf(acc);
    shpl[tid] = hpl;
    __syncthreads();

    float gh[3];
#pragma unroll
    for (int c = 0; c < 3; c++) {
        int i = c*NF + tid;
        float a = gbhh[i];
        const float* wrow = gwhh + (size_t)i*NF;
#pragma unroll 8
        for (int k = 0; k < NF; k++) a = fmaf(shpl[k], wrow[k], a);
        gh[c] = a;
    }
    const float* gi = g_gi + (size_t)b*384;
    float r = 1.f/(1.f + expf(-(gi[tid]       + gh[0])));
    float z = 1.f/(1.f + expf(-(gi[NF + tid]  + gh[1])));
    float n = tanhf(gi[2*NF + tid] + r*gh[2]);
    float hpr = (1.f - z)*n + z*hpl;
    g_hpr[(size_t)b*NF + tid] = hpr;
    out[(size_t)BS*NF + (size_t)b*NF + tid] = hpr;        // h_right
    if (tid == 0) out[(size_t)2*BS*NF + b] = hist_ts[b*HL + HL-1];
}

// ---------------- ODE (RK4, 8 steps) ----------------------------------------
__global__ void ode_kernel(const float* __restrict__ hist_ts,
                           const float* __restrict__ tnw,
                           const float* __restrict__ tnb,
                           const float* __restrict__ odeb,
                           float* __restrict__ out)
{
    int b = blockIdx.x, j = threadIdx.x;  // 128 threads
    __shared__ float y[NF];
    float t0 = hist_ts[b*HL + HL-2];
    float t1 = hist_ts[b*HL + HL-1];
    float ratio = t1 - t0;
    float z = g_hpr[(size_t)b*NF + j];
    float tw = tnw[j], tb = tnb[j], ob = odeb[j];
    const float ds = 1.f/ODE_STEPS;

    auto fstage = [&](float s, float zj) -> float {
        float te = cosf((s*ratio + t0)*tw + tb);
        __syncthreads();
        y[j] = zj + te;
        __syncthreads();
        float acc = ob;
        const float* wc = g_odewT + j;
#pragma unroll 8
        for (int k = 0; k < NF; k++) acc = fmaf(y[k], wc[k*NF], acc);
        return tanhf(acc) * ratio;
    };

    for (int i = 0; i < ODE_STEPS; i++) {
        float s = i * ds;
        float k1 = fstage(s,            z);
        float k2 = fstage(s + 0.5f*ds,  z + 0.5f*ds*k1);
        float k3 = fstage(s + 0.5f*ds,  z + 0.5f*ds*k2);
        float k4 = fstage(s + ds,       z + ds*k3);
        z += ds/6.f * (k1 + 2.f*k2 + 2.f*k3 + k4);
    }
    out[(size_t)b*NF + j] = z;   // h_left  (invalid_rows is provably always false)
}

// ---------------- host ------------------------------------------------------
extern "C" void kernel_launch(void* const* d_in, const int* in_sizes, int n_in,
                              void* d_out, int out_size)
{
    const int*   nids       = (const int*)  d_in[0];
    // d_in[1] = ts (unused by the reference)
    const int*   hist_nids  = (const int*)  d_in[2];
    const int*   aids       = (const int*)  d_in[3];
    const int*   eids       = (const int*)  d_in[4];
    const float* hist_ts    = (const float*)d_in[5];
    const int*   dirs       = (const int*)  d_in[6];
    const float* node_feat  = (const float*)d_in[7];
    const float* edge_feat  = (const float*)d_in[8];
    const float* anony_emb  = (const float*)d_in[9];
    const float* time_w     = (const float*)d_in[10];
    const float* time_b     = (const float*)d_in[11];
    const float* in_proj_w  = (const float*)d_in[12];
    const float* in_proj_b  = (const float*)d_in[13];
    const float* out_proj_w = (const float*)d_in[14];
    const float* out_proj_b = (const float*)d_in[15];
    const float* outfn_w    = (const float*)d_in[16];
    const float* outfn_b    = (const float*)d_in[17];
    const float* attn_wq    = (const float*)d_in[18];
    const float* attn_wk    = (const float*)d_in[19];
    const float* attn_wv    = (const float*)d_in[20];
    const float* merge_w    = (const float*)d_in[21];
    const float* merge_b    = (const float*)d_in[22];
    const float* gru_w_ih   = (const float*)d_in[23];
    // d_in[24] = gru_w_hh
    const float* gru_w_hh   = (const float*)d_in[24];
    const float* gru_b_ih   = (const float*)d_in[25];
    const float* gru_b_hh   = (const float*)d_in[26];
    const float* ode_w      = (const float*)d_in[27];
    const float* ode_b      = (const float*)d_in[28];
    const float* tnode_w    = (const float*)d_in[29];
    const float* tnode_b    = (const float*)d_in[30];

    float* out = (float*)d_out;

    float *p_full, *p_kv, *p_lef, *p_qlast, *p_ctx, *p_mha, *p_qn, *p_qh,
          *p_kh, *p_vh, *p_nb, *p_gi;
    cudaGetSymbolAddress((void**)&p_full,  g_full);
    cudaGetSymbolAddress((void**)&p_kv,    g_kv);
    cudaGetSymbolAddress((void**)&p_lef,   g_lef);
    cudaGetSymbolAddress((void**)&p_qlast, g_qlast);
    cudaGetSymbolAddress((void**)&p_ctx,   g_ctx);
    cudaGetSymbolAddress((void**)&p_mha,   g_mha);
    cudaGetSymbolAddress((void**)&p_qn,    g_qn);
    cudaGetSymbolAddress((void**)&p_qh,    g_qh);
    cudaGetSymbolAddress((void**)&p_kh,    g_kh);
    cudaGetSymbolAddress((void**)&p_vh,    g_vh);
    cudaGetSymbolAddress((void**)&p_nb,    g_nb);
    cudaGetSymbolAddress((void**)&p_gi,    g_gi);

    // 1. gather + time encode
    build_kernel<<<BS*HL, 128>>>(nids, hist_nids, aids, eids, hist_ts, dirs,
                                 node_feat, edge_feat, anony_emb, time_w, time_b);
    transpose_odew<<<128, 128>>>(ode_w);

    // 2. K|V projection: [81920,640] x [1280,640]^T  (in_proj rows 640..1919)
    sgemm_kernel<true><<<dim3(1280/128, BS*HL/128), 256>>>(
        BS*HL, 1280, DM, p_full, DM, in_proj_w + (size_t)DM*DM, p_kv, 1280,
        in_proj_b + DM);

    // 3. Q at last position only: [4096,640] x [640,640]^T
    sgemm_kernel<true><<<dim3(DM/128, BS/128), 256>>>(
        BS, DM, DM, p_full + (size_t)(HL-1)*DM, HL*DM, in_proj_w, p_qlast, DM,
        in_proj_b);

    // 4. attention 1 -> ctx
    attn1_kernel<<<BS, 256>>>(hist_nids);

    // 5. out_proj: [4096,640] x [640,640]^T
    sgemm_kernel<true><<<dim3(DM/128, BS/128), 256>>>(
        BS, DM, DM, p_ctx, DM, out_proj_w, p_mha, DM, out_proj_b);

    // 6. qn = mha @ outfn_w^T: [4096,640] x [128,640]^T
    sgemm_kernel<true><<<dim3(NF/128, BS/128), 256>>>(
        BS, NF, DM, p_mha, DM, outfn_w, p_qn, NF, outfn_b);

    // 7. kh/vh = nb @ attn_wk / attn_wv (NN): [81920,384] x [384,128]
    sgemm_kernel<false><<<dim3(NF/128, BS*HL/128), 256>>>(
        BS*HL, NF, 384, p_nb, 384, attn_wk, p_kh, NF, (const float*)nullptr);
    sgemm_kernel<false><<<dim3(NF/128, BS*HL/128), 256>>>(
        BS*HL, NF, 384, p_nb, 384, attn_wv, p_vh, NF, (const float*)nullptr);

    // 8. qh = qn @ attn_wq (NN): [4096,128] x [128,128]
    sgemm_kernel<false><<<dim3(NF/128, BS/128), 256>>>(
        BS, NF, NF, p_qn, NF, attn_wq, p_qh, NF, (const float*)nullptr);

    // 9. gi = lef @ gru_w_ih^T + b: [4096,512] x [384,512]^T
    sgemm_kernel<true><<<dim3(384/128, BS/128), 256>>>(
        BS, 384, DIN, p_lef, DIN, gru_w_ih, p_gi, 384, gru_b_ih);

    // 10. attention 2 + merge + GRU (writes h_right + ts to out)
    attn2_gru_kernel<<<BS, 128>>>(nids, hist_nids, hist_ts, node_feat,
                                  merge_w, merge_b, gru_w_hh, gru_b_hh, out);

    // 11. ODE RK4 (writes h_left to out)
    ode_kernel<<<BS, 128>>>(hist_ts, tnode_w, tnode_b, ode_b, out);
}

// round 3
// speedup vs baseline: 1.9776x; 1.9776x over previous
#include <cuda_runtime.h>
#include <cuda_bf16.h>
#include <math.h>
#include <stdint.h>

// Problem constants
#define BS 4096
#define HL 20
#define NF 128
#define EF 128
#define TF 128
#define DM 640          // 3*NF + EF + TF
#define DIN 512         // DM - TF
#define NHEAD 2
#define DH 320          // DM / NHEAD
#define ODE_STEPS 8

// ---------------- scratch (device globals; no allocation allowed) ----------
__device__ float g_full [(size_t)BS*HL*DM];     // full_vals  [BS,HL,640]
__device__ float g_nb   [(size_t)BS*HL*384];    // nb         [BS,HL,384]
__device__ float g_kv   [(size_t)BS*HL*1280];   // k|v        [BS,HL,1280]
__device__ float g_lef  [(size_t)BS*DIN];       // last_event_feat
__device__ float g_qlast[(size_t)BS*DM];
__device__ float g_ctx  [(size_t)BS*DM];
__device__ float g_mha  [(size_t)BS*DM];
__device__ float g_qn   [(size_t)BS*NF];
__device__ float g_qh   [(size_t)BS*NF];
__device__ float g_khv  [(size_t)BS*HL*256];    // kh|vh fused
__device__ float g_wkv  [384*256];              // attn_wk | attn_wv packed
__device__ float g_gi   [(size_t)BS*384];
__device__ float g_hpr  [(size_t)BS*NF];
__device__ float g_odewT[NF*NF];

__device__ __forceinline__ uint32_t f2tf(float x) {
    uint32_t u; asm("cvt.rna.tf32.f32 %0, %1;" : "=r"(u) : "f"(x)); return u;
}

// ---------------- build full_vals, nb, last_event_feat ---------------------
__global__ void build_kernel(const int* __restrict__ nids,
                             const int* __restrict__ hist_nids,
                             const int* __restrict__ aids,
                             const int* __restrict__ eids,
                             const float* __restrict__ hist_ts,
                             const int* __restrict__ dirs,
                             const float* __restrict__ node_feat,
                             const float* __restrict__ edge_feat,
                             const float* __restrict__ anony,
                             const float* __restrict__ tw,
                             const float* __restrict__ tb)
{
    int bl = blockIdx.x;            // b*HL + l
    int b  = bl / HL, l = bl % HL;
    int j  = threadIdx.x;           // 0..127
    int hn  = hist_nids[bl];
    int dir = dirs[bl];
    int nid = nids[b];
    int src = dir ? nid : hn;
    int dst = dir ? hn  : nid;
    float sv = node_feat[(size_t)src*NF + j];
    float dv = node_feat[(size_t)dst*NF + j];
    float av = anony[(size_t)aids[bl]*NF + j];
    float ev = edge_feat[(size_t)eids[bl]*EF + j];
    float dt = hist_ts[b*HL + HL-1] - hist_ts[bl];
    float tv = cosf(dt*tw[j] + tb[j]);

    float* fv = g_full + (size_t)bl*DM;
    if (l == HL-1) {
        float* lef = g_lef + (size_t)b*DIN;
        lef[j] = sv; lef[NF+j] = dv; lef[2*NF+j] = av; lef[3*NF+j] = ev;
        fv[j] = 0.f; fv[NF+j] = 0.f; fv[2*NF+j] = 0.f; fv[3*NF+j] = 0.f;
        fv[4*NF+j] = tv;
    } else {
        fv[j] = sv; fv[NF+j] = dv; fv[2*NF+j] = av; fv[3*NF+j] = ev;
        fv[4*NF+j] = tv;
    }
    float* nb = g_nb + (size_t)bl*384;
    nb[j]        = node_feat[(size_t)hn*NF + j];
    nb[NF + j]   = ev;
    nb[2*NF + j] = tv;
}

__global__ void transpose_odew(const float* __restrict__ w)
{
    int idx = blockIdx.x*128 + threadIdx.x;   // 16384 total
    int j = idx >> 7, k = idx & 127;
    g_odewT[k*NF + j] = w[idx];
}

__global__ void pack_wkv(const float* __restrict__ wk, const float* __restrict__ wv)
{
    int idx = blockIdx.x*128 + threadIdx.x;   // 384*128
    int k = idx >> 7, n = idx & 127;
    g_wkv[k*256 + n]       = wk[idx];
    g_wkv[k*256 + 128 + n] = wv[idx];
}

// ---------------- TF32 tensor-core GEMM -------------------------------------
// TRANSB=1: C[M,N] = A[M,K] * B[N,K]^T + bias   (B row-major (N,K))
// TRANSB=0: C[M,N] = A[M,K] * B[K,N]   + bias   (B row-major (K,N), stride N)
// requires M%128==0, N%128==0, K%16==0
template<bool TRANSB>
__global__ __launch_bounds__(256, 2)
void tgemm(int M, int N, int K,
           const float* __restrict__ A, int lda,
           const float* __restrict__ B,
           float* __restrict__ C, int ldc,
           const float* __restrict__ bias)
{
    __shared__ float As[2][16][136];
    __shared__ float Bs[2][16][136];
    int tid  = threadIdx.x;
    int row0 = blockIdx.y * 128;
    int col0 = blockIdx.x * 128;
    int warp = tid >> 5, lane = tid & 31;
    int wm = warp >> 2, wn = warp & 3;      // 2x4 warp grid
    int m0 = wm * 64, n0 = wn * 32;
    int g = lane >> 2, t = lane & 3;

    float c[4][4][4];
#pragma unroll
    for (int mi = 0; mi < 4; mi++)
#pragma unroll
        for (int ni = 0; ni < 4; ni++)
#pragma unroll
            for (int i = 0; i < 4; i++) c[mi][ni][i] = 0.f;

    int arow = tid >> 1, akq = (tid & 1) * 8;
    const float* Abase = A + (size_t)(row0 + arow) * lda + akq;
    float ra[8], rb[8];
    int T = K >> 4;

#define GLOAD(kt) {                                                          \
        const float* ap = Abase + (kt)*16;                                   \
        float4 v0 = *(const float4*)ap, v1 = *(const float4*)(ap + 4);       \
        ra[0]=v0.x; ra[1]=v0.y; ra[2]=v0.z; ra[3]=v0.w;                      \
        ra[4]=v1.x; ra[5]=v1.y; ra[6]=v1.z; ra[7]=v1.w;                      \
        if (TRANSB) {                                                        \
            const float* bp = B + (size_t)(col0 + arow)*K + (kt)*16 + akq;   \
            float4 u0 = *(const float4*)bp, u1 = *(const float4*)(bp + 4);   \
            rb[0]=u0.x; rb[1]=u0.y; rb[2]=u0.z; rb[3]=u0.w;                  \
            rb[4]=u1.x; rb[5]=u1.y; rb[6]=u1.z; rb[7]=u1.w;                  \
        } else {                                                             \
            int bk = tid >> 5, bn = (tid & 31) * 4;                          \
            const float* bp = B + (size_t)((kt)*16 + bk)*N + col0 + bn;      \
            float4 u0 = *(const float4*)bp;                                  \
            float4 u1 = *(const float4*)(bp + (size_t)8*N);                  \
            rb[0]=u0.x; rb[1]=u0.y; rb[2]=u0.z; rb[3]=u0.w;                  \
            rb[4]=u1.x; rb[5]=u1.y; rb[6]=u1.z; rb[7]=u1.w;                  \
        }                                                                    \
    }

#define SSTORE(buf) {                                                        \
        _Pragma("unroll")                                                    \
        for (int i = 0; i < 8; i++)                                          \
            As[buf][akq + i][arow] = __uint_as_float(f2tf(ra[i]));           \
        if (TRANSB) {                                                        \
            _Pragma("unroll")                                                \
            for (int i = 0; i < 8; i++)                                      \
                Bs[buf][akq + i][arow] = __uint_as_float(f2tf(rb[i]));       \
        } else {                                                             \
            int bk = tid >> 5, bn = (tid & 31) * 4;                          \
            _Pragma("unroll")                                                \
            for (int i = 0; i < 4; i++)                                      \
                Bs[buf][bk][bn + i]   = __uint_as_float(f2tf(rb[i]));        \
            _Pragma("unroll")                                                \
            for (int i = 0; i < 4; i++)                                      \
                Bs[buf][bk + 8][bn+i] = __uint_as_float(f2tf(rb[4 + i]));    \
        }                                                                    \
    }

    GLOAD(0); SSTORE(0); __syncthreads();

    for (int kt = 0; kt < T; kt++) {
        int buf = kt & 1;
        if (kt + 1 < T) GLOAD(kt + 1);
        // compute from smem buf
#pragma unroll
        for (int ks = 0; ks < 16; ks += 8) {
            uint32_t a[4][4], bb[4][2];
#pragma unroll
            for (int mi = 0; mi < 4; mi++) {
                int rm = m0 + mi*16 + g;
                a[mi][0] = __float_as_uint(As[buf][ks + t    ][rm    ]);
                a[mi][1] = __float_as_uint(As[buf][ks + t    ][rm + 8]);
                a[mi][2] = __float_as_uint(As[buf][ks + t + 4][rm    ]);
                a[mi][3] = __float_as_uint(As[buf][ks + t + 4][rm + 8]);
            }
#pragma unroll
            for (int ni = 0; ni < 4; ni++) {
                int cn = n0 + ni*8 + g;
                bb[ni][0] = __float_as_uint(Bs[buf][ks + t    ][cn]);
                bb[ni][1] = __float_as_uint(Bs[buf][ks + t + 4][cn]);
            }
#pragma unroll
            for (int mi = 0; mi < 4; mi++)
#pragma unroll
                for (int ni = 0; ni < 4; ni++) {
                    asm volatile(
                        "mma.sync.aligned.m16n8k8.row.col.f32.tf32.tf32.f32 "
                        "{%0,%1,%2,%3},{%4,%5,%6,%7},{%8,%9},{%0,%1,%2,%3};\n"
                        : "+f"(c[mi][ni][0]), "+f"(c[mi][ni][1]),
                          "+f"(c[mi][ni][2]), "+f"(c[mi][ni][3])
                        : "r"(a[mi][0]), "r"(a[mi][1]), "r"(a[mi][2]), "r"(a[mi][3]),
                          "r"(bb[ni][0]), "r"(bb[ni][1]));
                }
        }
        if (kt + 1 < T) SSTORE(buf ^ 1);
        __syncthreads();
    }

    // epilogue
#pragma unroll
    for (int mi = 0; mi < 4; mi++) {
        size_t r1 = (size_t)(row0 + m0 + mi*16 + g);
        size_t r2 = r1 + 8;
#pragma unroll
        for (int ni = 0; ni < 4; ni++) {
            int cc = col0 + n0 + ni*8 + 2*t;
            float b0 = 0.f, b1 = 0.f;
            if (bias) { b0 = bias[cc]; b1 = bias[cc + 1]; }
            *(float2*)&C[r1*ldc + cc] = make_float2(c[mi][ni][0] + b0, c[mi][ni][1] + b1);
            *(float2*)&C[r2*ldc + cc] = make_float2(c[mi][ni][2] + b0, c[mi][ni][3] + b1);
        }
    }
#undef GLOAD
#undef SSTORE
}

// ---------------- attention 1 (query = last position) ----------------------
__global__ void attn1_kernel(const int* __restrict__ hist_nids)
{
    int b = blockIdx.x, tid = threadIdx.x;   // 256 threads
    __shared__ float sq[DM];
    __shared__ float sS[NHEAD*HL];
    __shared__ float sA[NHEAD*HL];
    for (int d = tid; d < DM; d += 256) sq[d] = g_qlast[(size_t)b*DM + d];
    __syncthreads();

    int warp = tid >> 5, lane = tid & 31;
    for (int p = warp; p < NHEAD*HL; p += 8) {
        int h = p / HL, m = p % HL;
        const float* krow = g_kv + (size_t)(b*HL + m)*1280 + h*DH;
        const float* qrow = sq + h*DH;
        float s = 0.f;
#pragma unroll
        for (int i = 0; i < 10; i++) { int d = lane + i*32; s += qrow[d]*krow[d]; }
#pragma unroll
        for (int o = 16; o; o >>= 1) s += __shfl_xor_sync(0xffffffffu, s, o);
        if (!lane) sS[p] = s * 0.05590169943749474f;   // 1/sqrt(320)
    }
    __syncthreads();
    if (tid < NHEAD) {
        int h = tid;
        float sc[HL], mx = -1e30f;
        for (int m = 0; m < HL; m++) {
            float v = sS[h*HL + m];
            if (hist_nids[b*HL + m] == 0 && m != HL-1) v = -1e9f;
            sc[m] = v; mx = fmaxf(mx, v);
        }
        float sum = 0.f;
        for (int m = 0; m < HL; m++) { float e = expf(sc[m]-mx); sc[m] = e; sum += e; }
        float inv = 1.f/sum;
        for (int m = 0; m < HL; m++) sA[h*HL + m] = sc[m]*inv;
    }
    __syncthreads();
    for (int d = tid; d < DM; d += 256) {
        int h = d / DH;
        const float* vbase = g_kv + (size_t)b*HL*1280 + 640 + d;
        float accv = 0.f;
#pragma unroll
        for (int m = 0; m < HL; m++) accv += sA[h*HL + m] * vbase[(size_t)m*1280];
        g_ctx[(size_t)b*DM + d] = accv;
    }
}

// ---------------- attention 2 + merge + GRU ---------------------------------
__global__ void attn2_gru_kernel(const int* __restrict__ nids,
                                 const int* __restrict__ hist_nids,
                                 const float* __restrict__ hist_ts,
                                 const float* __restrict__ node_feat,
                                 const float* __restrict__ merge_w,
                                 const float* __restrict__ merge_b,
                                 const float* __restrict__ gwhh,
                                 const float* __restrict__ gbhh,
                                 float* __restrict__ out)
{
    int b = blockIdx.x, tid = threadIdx.x;   // 128 threads
    __shared__ float sqh[NF], ssc[HL], sa[HL], scat[2*NF], shpl[NF];
    sqh[tid] = g_qh[(size_t)b*NF + tid];
    __syncthreads();
    int warp = tid >> 5, lane = tid & 31;
    for (int l = warp; l < HL; l += 4) {
        const float* kr = g_khv + (size_t)(b*HL + l)*256;
        float s = 0.f;
#pragma unroll
        for (int i = 0; i < 4; i++) { int d = lane + i*32; s += sqh[d]*kr[d]; }
#pragma unroll
        for (int o = 16; o; o >>= 1) s += __shfl_xor_sync(0xffffffffu, s, o);
        if (!lane) ssc[l] = s * 0.08838834764831845f;  // 1/sqrt(128)
    }
    __syncthreads();
    if (tid == 0) {
        float sc[HL], mx = -1e30f;
        for (int l = 0; l < HL; l++) {
            float v = ssc[l];
            if (hist_nids[b*HL + l] == 0 && l != HL-1) v = -1e9f;
            sc[l] = v; mx = fmaxf(mx, v);
        }
        float sum = 0.f;
        for (int l = 0; l < HL; l++) { float e = expf(sc[l]-mx); sc[l] = e; sum += e; }
        float inv = 1.f/sum;
        for (int l = 0; l < HL; l++) sa[l] = sc[l]*inv;
    }
    __syncthreads();
    float c2 = 0.f;
#pragma unroll
    for (int l = 0; l < HL; l++) c2 += sa[l] * g_khv[(size_t)(b*HL + l)*256 + 128 + tid];
    scat[tid]      = c2;
    scat[NF + tid] = node_feat[(size_t)nids[b]*NF + tid];
    __syncthreads();

    float acc = merge_b[tid];
#pragma unroll 8
    for (int k = 0; k < 2*NF; k++) acc = fmaf(scat[k], merge_w[k*NF + tid], acc);
    float hpl = tanhf(acc);
    shpl[tid] = hpl;
    __syncthreads();

    float gh[3];
#pragma unroll
    for (int c = 0; c < 3; c++) {
        int i = c*NF + tid;
        float a = gbhh[i];
        const float* wrow = gwhh + (size_t)i*NF;
#pragma unroll 8
        for (int k = 0; k < NF; k++) a = fmaf(shpl[k], wrow[k], a);
        gh[c] = a;
    }
    const float* gi = g_gi + (size_t)b*384;
    float r = 1.f/(1.f + expf(-(gi[tid]       + gh[0])));
    float z = 1.f/(1.f + expf(-(gi[NF + tid]  + gh[1])));
    float n = tanhf(gi[2*NF + tid] + r*gh[2]);
    float hpr = (1.f - z)*n + z*hpl;
    g_hpr[(size_t)b*NF + tid] = hpr;
    out[(size_t)BS*NF + (size_t)b*NF + tid] = hpr;        // h_right
    if (tid == 0) out[(size_t)2*BS*NF + b] = hist_ts[b*HL + HL-1];
}

// ---------------- ODE (RK4, 8 steps) ----------------------------------------
__global__ void ode_kernel(const float* __restrict__ hist_ts,
                           const float* __restrict__ tnw,
                           const float* __restrict__ tnb,
                           const float* __restrict__ odeb,
                           float* __restrict__ out)
{
    int b = blockIdx.x, j = threadIdx.x;  // 128 threads
    __shared__ float y[NF];
    float t0 = hist_ts[b*HL + HL-2];
    float t1 = hist_ts[b*HL + HL-1];
    float ratio = t1 - t0;
    float z = g_hpr[(size_t)b*NF + j];
    float tw = tnw[j], tb = tnb[j], ob = odeb[j];
    const float ds = 1.f/ODE_STEPS;

    auto fstage = [&](float s, float zj) -> float {
        float te = cosf((s*ratio + t0)*tw + tb);
        __syncthreads();
        y[j] = zj + te;
        __syncthreads();
        float acc = ob;
        const float* wc = g_odewT + j;
#pragma unroll 8
        for (int k = 0; k < NF; k++) acc = fmaf(y[k], wc[k*NF], acc);
        return tanhf(acc) * ratio;
    };

    for (int i = 0; i < ODE_STEPS; i++) {
        float s = i * ds;
        float k1 = fstage(s,            z);
        float k2 = fstage(s + 0.5f*ds,  z + 0.5f*ds*k1);
        float k3 = fstage(s + 0.5f*ds,  z + 0.5f*ds*k2);
        float k4 = fstage(s + ds,       z + ds*k3);
        z += ds/6.f * (k1 + 2.f*k2 + 2.f*k3 + k4);
    }
    out[(size_t)b*NF + j] = z;   // h_left (invalid_rows provably always false)
}

// ---------------- host ------------------------------------------------------
extern "C" void kernel_launch(void* const* d_in, const int* in_sizes, int n_in,
                              void* d_out, int out_size)
{
    const int*   nids       = (const int*)  d_in[0];
    const int*   hist_nids  = (const int*)  d_in[2];
    const int*   aids       = (const int*)  d_in[3];
    const int*   eids       = (const int*)  d_in[4];
    const float* hist_ts    = (const float*)d_in[5];
    const int*   dirs       = (const int*)  d_in[6];
    const float* node_feat  = (const float*)d_in[7];
    const float* edge_feat  = (const float*)d_in[8];
    const float* anony_emb  = (const float*)d_in[9];
    const float* time_w     = (const float*)d_in[10];
    const float* time_b     = (const float*)d_in[11];
    const float* in_proj_w  = (const float*)d_in[12];
    const float* in_proj_b  = (const float*)d_in[13];
    const float* out_proj_w = (const float*)d_in[14];
    const float* out_proj_b = (const float*)d_in[15];
    const float* outfn_w    = (const float*)d_in[16];
    const float* outfn_b    = (const float*)d_in[17];
    const float* attn_wq    = (const float*)d_in[18];
    const float* attn_wk    = (const float*)d_in[19];
    const float* attn_wv    = (const float*)d_in[20];
    const float* merge_w    = (const float*)d_in[21];
    const float* merge_b    = (const float*)d_in[22];
    const float* gru_w_ih   = (const float*)d_in[23];
    const float* gru_w_hh   = (const float*)d_in[24];
    const float* gru_b_ih   = (const float*)d_in[25];
    const float* gru_b_hh   = (const float*)d_in[26];
    const float* ode_w      = (const float*)d_in[27];
    const float* ode_b      = (const float*)d_in[28];
    const float* tnode_w    = (const float*)d_in[29];
    const float* tnode_b    = (const float*)d_in[30];

    float* out = (float*)d_out;

    float *p_full, *p_kv, *p_lef, *p_qlast, *p_ctx, *p_mha, *p_qn, *p_qh,
          *p_khv, *p_wkv, *p_nb, *p_gi;
    cudaGetSymbolAddress((void**)&p_full,  g_full);
    cudaGetSymbolAddress((void**)&p_kv,    g_kv);
    cudaGetSymbolAddress((void**)&p_lef,   g_lef);
    cudaGetSymbolAddress((void**)&p_qlast, g_qlast);
    cudaGetSymbolAddress((void**)&p_ctx,   g_ctx);
    cudaGetSymbolAddress((void**)&p_mha,   g_mha);
    cudaGetSymbolAddress((void**)&p_qn,    g_qn);
    cudaGetSymbolAddress((void**)&p_qh,    g_qh);
    cudaGetSymbolAddress((void**)&p_khv,   g_khv);
    cudaGetSymbolAddress((void**)&p_wkv,   g_wkv);
    cudaGetSymbolAddress((void**)&p_nb,    g_nb);
    cudaGetSymbolAddress((void**)&p_gi,    g_gi);

    // 1. gather + time encode (+ weight packing)
    build_kernel<<<BS*HL, 128>>>(nids, hist_nids, aids, eids, hist_ts, dirs,
                                 node_feat, edge_feat, anony_emb, time_w, time_b);
    transpose_odew<<<128, 128>>>(ode_w);
    pack_wkv<<<384, 128>>>(attn_wk, attn_wv);

    // 2. K|V projection: [81920,640] x [1280,640]^T
    tgemm<true><<<dim3(1280/128, BS*HL/128), 256>>>(
        BS*HL, 1280, DM, p_full, DM, in_proj_w + (size_t)DM*DM, p_kv, 1280,
        in_proj_b + DM);

    // 3. Q at last position only: [4096,640] x [640,640]^T
    tgemm<true><<<dim3(DM/128, BS/128), 256>>>(
        BS, DM, DM, p_full + (size_t)(HL-1)*DM, HL*DM, in_proj_w, p_qlast, DM,
        in_proj_b);

    // 4. attention 1 -> ctx
    attn1_kernel<<<BS, 256>>>(hist_nids);

    // 5. out_proj: [4096,640] x [640,640]^T
    tgemm<true><<<dim3(DM/128, BS/128), 256>>>(
        BS, DM, DM, p_ctx, DM, out_proj_w, p_mha, DM, out_proj_b);

    // 6. qn = mha @ outfn_w^T: [4096,640] x [128,640]^T
    tgemm<true><<<dim3(NF/128, BS/128), 256>>>(
        BS, NF, DM, p_mha, DM, outfn_w, p_qn, NF, outfn_b);

    // 7. kh|vh = nb @ [attn_wk|attn_wv] (NN): [81920,384] x [384,256]
    tgemm<false><<<dim3(256/128, BS*HL/128), 256>>>(
        BS*HL, 256, 384, p_nb, 384, p_wkv, p_khv, 256, (const float*)nullptr);

    // 8. qh = qn @ attn_wq (NN): [4096,128] x [128,128]
    tgemm<false><<<dim3(NF/128, BS/128), 256>>>(
        BS, NF, NF, p_qn, NF, attn_wq, p_qh, NF, (const float*)nullptr);

    // 9. gi = lef @ gru_w_ih^T + b: [4096,512] x [384,512]^T
    tgemm<true><<<dim3(384/128, BS/128), 256>>>(
        BS, 384, DIN, p_lef, DIN, gru_w_ih, p_gi, 384, gru_b_ih);

    // 10. attention 2 + merge + GRU (writes h_right + ts to out)
    attn2_gru_kernel<<<BS, 128>>>(nids, hist_nids, hist_ts, node_feat,
                                  merge_w, merge_b, gru_w_hh, gru_b_hh, out);

    // 11. ODE RK4 (writes h_left to out)
    ode_kernel<<<BS, 128>>>(hist_ts, tnode_w, tnode_b, ode_b, out);
}